// round 8
// baseline (speedup 1.0000x reference)
#include <cuda_runtime.h>
#include <cuda_fp16.h>

#define D 64
#define NMAX 100000
#define EMAX 1280000
#define SCAN_BS 1024

__device__ int    g_degi[NMAX];       // out-degree (int)
__device__ int    g_rowptr[NMAX];     // CSR row start
__device__ int    g_cur[NMAX];        // scatter cursors
__device__ int    g_bsums[128];       // scan block sums
__device__ float  g_sw[NMAX];         // per-node sum of edge weights
__device__ int2   g_epack[EMAX];      // {dst node, weight bits} in CSR order
__device__ __half g_xh[NMAX * D];     // fp16 copy of embeddings (12.8 MB)

typedef unsigned long long u64;
__device__ __forceinline__ u64 ffma2(u64 a, u64 b, u64 c) {
    u64 d;
    asm("fma.rn.f32x2 %0, %1, %2, %3;" : "=l"(d) : "l"(a), "l"(b), "l"(c));
    return d;
}
__device__ __forceinline__ u64 pack2(float lo, float hi) {
    u64 d;
    asm("mov.b64 %0, {%1, %2};" : "=l"(d) : "f"(lo), "f"(hi));
    return d;
}
__device__ __forceinline__ float lo32(u64 v) { return __uint_as_float((unsigned)v); }
__device__ __forceinline__ float hi32(u64 v) { return __uint_as_float((unsigned)(v >> 32)); }

// ---------------------------------------------------------------------------
// 0. convert embeddings to fp16 + zero degree counters (fused)
// ---------------------------------------------------------------------------
__global__ void xh_kernel(const float4* __restrict__ X4, int total8, int N) {
    int i = blockIdx.x * blockDim.x + threadIdx.x;
    if (i < N) g_degi[i] = 0;
    if (i >= total8) return;
    float4 a = X4[i * 2];
    float4 b = X4[i * 2 + 1];
    __half2 h0 = __floats2half2_rn(a.x, a.y);
    __half2 h1 = __floats2half2_rn(a.z, a.w);
    __half2 h2 = __floats2half2_rn(b.x, b.y);
    __half2 h3 = __floats2half2_rn(b.z, b.w);
    uint4 o;
    o.x = *reinterpret_cast<unsigned*>(&h0);
    o.y = *reinterpret_cast<unsigned*>(&h1);
    o.z = *reinterpret_cast<unsigned*>(&h2);
    o.w = *reinterpret_cast<unsigned*>(&h3);
    reinterpret_cast<uint4*>(g_xh)[i] = o;
}

// ---------------------------------------------------------------------------
// 1. degree histogram over source nodes
// ---------------------------------------------------------------------------
__global__ void deg_kernel(const int* __restrict__ n1, int E) {
    int e = blockIdx.x * blockDim.x + threadIdx.x;
    if (e < E) atomicAdd(&g_degi[n1[e]], 1);
}

// ---------------------------------------------------------------------------
// 2. per-block scan of g_degi via warp shuffles (2 barriers total)
// ---------------------------------------------------------------------------
__global__ void scan1_kernel(int N) {
    __shared__ int wsums[32];
    int tid = threadIdx.x;
    int lane = tid & 31;
    int w = tid >> 5;
    int i = blockIdx.x * SCAN_BS + tid;
    int v = (i < N) ? g_degi[i] : 0;
    int inc = v;
    #pragma unroll
    for (int off = 1; off < 32; off <<= 1) {
        int t = __shfl_up_sync(0xffffffffu, inc, off);
        if (lane >= off) inc += t;
    }
    if (lane == 31) wsums[w] = inc;
    __syncthreads();
    if (tid < 32) {
        int s = wsums[tid];
        int si = s;
        #pragma unroll
        for (int off = 1; off < 32; off <<= 1) {
            int t = __shfl_up_sync(0xffffffffu, si, off);
            if (lane >= off) si += t;
        }
        wsums[tid] = si - s;   // exclusive warp base
    }
    __syncthreads();
    if (i < N) g_rowptr[i] = wsums[w] + inc - v;      // exclusive within block
    if (tid == SCAN_BS - 1) g_bsums[blockIdx.x] = wsums[31] + inc;
}

// ---------------------------------------------------------------------------
// 3. fused block-sum scan + apply: each block redundantly scans <=128 sums.
// ---------------------------------------------------------------------------
__global__ void scan3_kernel(int N, int nb) {
    __shared__ int wsum[4];
    __shared__ int pref;
    int tid = threadIdx.x;
    if (tid < 128) {
        int lane = tid & 31;
        int w = tid >> 5;
        int v = (tid < nb) ? g_bsums[tid] : 0;
        int inc = v;
        #pragma unroll
        for (int off = 1; off < 32; off <<= 1) {
            int t = __shfl_up_sync(0xffffffffu, inc, off);
            if (lane >= off) inc += t;
        }
        if (lane == 31) wsum[w] = inc;
    }
    __syncthreads();
    if (tid < 128) {
        int lane = tid & 31;
        int w = tid >> 5;
        int v = (tid < nb) ? g_bsums[tid] : 0;
        int inc = v;
        #pragma unroll
        for (int off = 1; off < 32; off <<= 1) {
            int t = __shfl_up_sync(0xffffffffu, inc, off);
            if (lane >= off) inc += t;
        }
        int base = 0;
        #pragma unroll
        for (int k = 0; k < 4; k++) base += (k < w) ? wsum[k] : 0;
        if (tid == blockIdx.x) pref = base + inc - v;   // exclusive prefix
    }
    __syncthreads();
    int i = blockIdx.x * SCAN_BS + tid;
    if (i < N) {
        int r = g_rowptr[i] + pref;
        g_rowptr[i] = r;
        g_cur[i] = r;
    }
}

// ---------------------------------------------------------------------------
// 4. scatter edges into CSR order with precomputed weights
// ---------------------------------------------------------------------------
__global__ void scatter_kernel(const int* __restrict__ n1,
                               const int* __restrict__ n2,
                               const float* __restrict__ dist,
                               int E) {
    int e = blockIdx.x * blockDim.x + threadIdx.x;
    if (e >= E) return;
    int a = n1[e];
    int c = n2[e];
    float dv = dist[e];
    float w = rsqrtf(__int2float_rn(g_degi[a]) * __int2float_rn(g_degi[c])) * __expf(-dv * dv);
    int pos = atomicAdd(&g_cur[a], 1);
    g_epack[pos] = make_int2(c, __float_as_int(w));
}

// ---------------------------------------------------------------------------
// 5. warp-per-node gather over fp16 embeddings. One __half2 per lane per
//    edge; unroll-4 for MLP; zero inter-node divergence. Single write.
// ---------------------------------------------------------------------------
__global__ __launch_bounds__(256) void gather_kernel(float* __restrict__ out, int N) {
    int v = (blockIdx.x * blockDim.x + threadIdx.x) >> 5;   // node = warp
    int lane = threadIdx.x & 31;
    if (v >= N) return;

    int start = g_rowptr[v];
    int cnt = g_degi[v];
    const unsigned* Xh2 = reinterpret_cast<const unsigned*>(g_xh);

    float ax = 0.f, ay = 0.f, swl = 0.f;
    int j = 0;
    for (; j + 4 <= cnt; j += 4) {
        int2 p0 = g_epack[start + j];
        int2 p1 = g_epack[start + j + 1];
        int2 p2 = g_epack[start + j + 2];
        int2 p3 = g_epack[start + j + 3];
        unsigned h0 = Xh2[(size_t)p0.x * 32 + lane];
        unsigned h1 = Xh2[(size_t)p1.x * 32 + lane];
        unsigned h2 = Xh2[(size_t)p2.x * 32 + lane];
        unsigned h3 = Xh2[(size_t)p3.x * 32 + lane];
        float w0 = __int_as_float(p0.y), w1 = __int_as_float(p1.y);
        float w2 = __int_as_float(p2.y), w3 = __int_as_float(p3.y);
        swl += (w0 + w1) + (w2 + w3);
        float2 f0 = __half22float2(*reinterpret_cast<__half2*>(&h0));
        float2 f1 = __half22float2(*reinterpret_cast<__half2*>(&h1));
        float2 f2 = __half22float2(*reinterpret_cast<__half2*>(&h2));
        float2 f3 = __half22float2(*reinterpret_cast<__half2*>(&h3));
        ax = fmaf(w0, f0.x, ax);  ay = fmaf(w0, f0.y, ay);
        ax = fmaf(w1, f1.x, ax);  ay = fmaf(w1, f1.y, ay);
        ax = fmaf(w2, f2.x, ax);  ay = fmaf(w2, f2.y, ay);
        ax = fmaf(w3, f3.x, ax);  ay = fmaf(w3, f3.y, ay);
    }
    for (; j < cnt; j++) {
        int2 p = g_epack[start + j];
        float w = __int_as_float(p.y);
        unsigned h = Xh2[(size_t)p.x * 32 + lane];
        swl += w;
        float2 f = __half22float2(*reinterpret_cast<__half2*>(&h));
        ax = fmaf(w, f.x, ax);  ay = fmaf(w, f.y, ay);
    }
    reinterpret_cast<float2*>(out)[(size_t)v * 32 + lane] = make_float2(ax, ay);
    if (lane == 0) g_sw[v] = swl;
}

// ---------------------------------------------------------------------------
// 6. Post: y = agg @ W^T + sw*b, leaky_relu, L2 normalize. In-place on out.
// ---------------------------------------------------------------------------
#define PB_ROWS 64
#define WPITCH 33
#define XPITCH 66
__global__ __launch_bounds__(256) void post_kernel(const float* __restrict__ W,
                                                   const float* __restrict__ b,
                                                   float* __restrict__ out, int N) {
    __shared__ u64 Ws2[D * WPITCH];
    __shared__ u64 Xst2[(D / 2) * XPITCH];
    __shared__ float sws[PB_ROWS];

    int tid = threadIdx.x;
    int wid = tid >> 5;
    int l = tid & 31;
    int row0 = blockIdx.x * PB_ROWS;

    const u64* W2 = reinterpret_cast<const u64*>(W);
    #pragma unroll
    for (int i = tid; i < D * (D / 2); i += 256) {
        int j = i >> 5, kp = i & 31;
        Ws2[j * WPITCH + kp] = W2[i];
    }
    const u64* O2 = reinterpret_cast<const u64*>(out);
    #pragma unroll
    for (int i = tid; i < PB_ROWS * (D / 2); i += 256) {
        int r = i >> 5, kp = i & 31;
        int row = row0 + r;
        Xst2[kp * XPITCH + r] = (row < N) ? O2[(size_t)row * (D / 2) + kp] : 0ull;
    }
    if (tid < PB_ROWS) {
        int row = row0 + tid;
        sws[tid] = (row < N) ? g_sw[row] : 0.0f;
    }
    __syncthreads();

    int r0 = wid * 8;
    float bl = b[l], bh = b[l + 32];
    u64 accL[8], accH[8];
    #pragma unroll
    for (int r = 0; r < 8; r++) {
        float s = sws[r0 + r];
        accL[r] = pack2(s * bl, 0.0f);
        accH[r] = pack2(s * bh, 0.0f);
    }

    const u64* wrowL = &Ws2[l * WPITCH];
    const u64* wrowH = &Ws2[(l + 32) * WPITCH];
    #pragma unroll 2
    for (int kp = 0; kp < D / 2; kp++) {
        const u64* xr = &Xst2[kp * XPITCH + r0];
        ulonglong2 x01 = *reinterpret_cast<const ulonglong2*>(xr);
        ulonglong2 x23 = *reinterpret_cast<const ulonglong2*>(xr + 2);
        ulonglong2 x45 = *reinterpret_cast<const ulonglong2*>(xr + 4);
        ulonglong2 x67 = *reinterpret_cast<const ulonglong2*>(xr + 6);
        u64 wl = wrowL[kp];
        u64 wh = wrowH[kp];
        accL[0] = ffma2(x01.x, wl, accL[0]);  accH[0] = ffma2(x01.x, wh, accH[0]);
        accL[1] = ffma2(x01.y, wl, accL[1]);  accH[1] = ffma2(x01.y, wh, accH[1]);
        accL[2] = ffma2(x23.x, wl, accL[2]);  accH[2] = ffma2(x23.x, wh, accH[2]);
        accL[3] = ffma2(x23.y, wl, accL[3]);  accH[3] = ffma2(x23.y, wh, accH[3]);
        accL[4] = ffma2(x45.x, wl, accL[4]);  accH[4] = ffma2(x45.x, wh, accH[4]);
        accL[5] = ffma2(x45.y, wl, accL[5]);  accH[5] = ffma2(x45.y, wh, accH[5]);
        accL[6] = ffma2(x67.x, wl, accL[6]);  accH[6] = ffma2(x67.x, wh, accH[6]);
        accL[7] = ffma2(x67.y, wl, accL[7]);  accH[7] = ffma2(x67.y, wh, accH[7]);
    }

    #pragma unroll
    for (int r = 0; r < 8; r++) {
        float vL = lo32(accL[r]) + hi32(accL[r]);
        float vH = lo32(accH[r]) + hi32(accH[r]);
        vL = (vL >= 0.0f) ? vL : 0.01f * vL;
        vH = (vH >= 0.0f) ? vH : 0.01f * vH;
        float ss = vL * vL + vH * vH;
        #pragma unroll
        for (int o = 16; o > 0; o >>= 1) ss += __shfl_xor_sync(0xffffffffu, ss, o);
        int row = row0 + r0 + r;
        if (row < N) {
            float inv = 1.0f / fmaxf(sqrtf(ss), 1e-12f);
            out[(size_t)row * D + l]      = vL * inv;
            out[(size_t)row * D + l + 32] = vH * inv;
        }
    }
}

// ---------------------------------------------------------------------------
// Launch
// ---------------------------------------------------------------------------
extern "C" void kernel_launch(void* const* d_in, const int* in_sizes, int n_in,
                              void* d_out, int out_size) {
    const float* poi  = (const float*)d_in[0];
    const int*   eidx = (const int*)d_in[1];
    const float* dist = (const float*)d_in[2];
    const float* W    = (const float*)d_in[3];
    const float* b    = (const float*)d_in[4];
    float* out = (float*)d_out;

    int N = in_sizes[0] / D;
    int E = in_sizes[1] / 2;
    const int* n1 = eidx;
    const int* n2 = eidx + E;
    int nb = (N + SCAN_BS - 1) / SCAN_BS;

    {
        int total8 = N * (D / 8);
        xh_kernel<<<(total8 + 255) / 256, 256>>>((const float4*)poi, total8, N);
    }
    deg_kernel<<<(E + 255) / 256, 256>>>(n1, E);
    scan1_kernel<<<nb, SCAN_BS>>>(N);
    scan3_kernel<<<nb, SCAN_BS>>>(N, nb);
    scatter_kernel<<<(E + 255) / 256, 256>>>(n1, n2, dist, E);
    {
        long long threads = (long long)N * 32;
        int blocks = (int)((threads + 255) / 256);
        gather_kernel<<<blocks, 256>>>(out, N);
    }
    {
        int blocks = (N + PB_ROWS - 1) / PB_ROWS;
        post_kernel<<<blocks, 256>>>(W, b, out, N);
    }
}

// round 9
// speedup vs baseline: 1.1102x; 1.1102x over previous
#include <cuda_runtime.h>
#include <cuda_fp16.h>

#define D 64
#define NMAX 100000
#define EMAX 1280000
#define SCAN_BS 1024

__device__ int   g_degi[NMAX];     // out-degree (int)
__device__ int   g_rowptr[NMAX];   // CSR row start
__device__ int   g_cur[NMAX];      // scatter cursors
__device__ int   g_bsums[128];     // scan block sums
__device__ float g_sw[NMAX];       // per-node sum of edge weights
__device__ int2  g_epack[EMAX];    // {dst node, weight bits} in CSR order

typedef unsigned long long u64;
__device__ __forceinline__ u64 ffma2(u64 a, u64 b, u64 c) {
    u64 d;
    asm("fma.rn.f32x2 %0, %1, %2, %3;" : "=l"(d) : "l"(a), "l"(b), "l"(c));
    return d;
}
__device__ __forceinline__ u64 pack2(float lo, float hi) {
    u64 d;
    asm("mov.b64 %0, {%1, %2};" : "=l"(d) : "f"(lo), "f"(hi));
    return d;
}
__device__ __forceinline__ float lo32(u64 v) { return __uint_as_float((unsigned)v); }
__device__ __forceinline__ float hi32(u64 v) { return __uint_as_float((unsigned)(v >> 32)); }

// ---------------------------------------------------------------------------
// 1. zero degree counters
// ---------------------------------------------------------------------------
__global__ void zero_deg_kernel(int N) {
    int i = blockIdx.x * blockDim.x + threadIdx.x;
    if (i < N) g_degi[i] = 0;
}

// ---------------------------------------------------------------------------
// 2. degree histogram over source nodes
// ---------------------------------------------------------------------------
__global__ void deg_kernel(const int* __restrict__ n1, int E) {
    int e = blockIdx.x * blockDim.x + threadIdx.x;
    if (e < E) atomicAdd(&g_degi[n1[e]], 1);
}

// ---------------------------------------------------------------------------
// 3. per-block scan of g_degi via warp shuffles (2 barriers total)
// ---------------------------------------------------------------------------
__global__ void scan1_kernel(int N) {
    __shared__ int wsums[32];
    int tid = threadIdx.x;
    int lane = tid & 31;
    int w = tid >> 5;
    int i = blockIdx.x * SCAN_BS + tid;
    int v = (i < N) ? g_degi[i] : 0;
    int inc = v;
    #pragma unroll
    for (int off = 1; off < 32; off <<= 1) {
        int t = __shfl_up_sync(0xffffffffu, inc, off);
        if (lane >= off) inc += t;
    }
    if (lane == 31) wsums[w] = inc;
    __syncthreads();
    if (tid < 32) {
        int s = wsums[tid];
        int si = s;
        #pragma unroll
        for (int off = 1; off < 32; off <<= 1) {
            int t = __shfl_up_sync(0xffffffffu, si, off);
            if (lane >= off) si += t;
        }
        wsums[tid] = si - s;   // exclusive warp base
    }
    __syncthreads();
    if (i < N) g_rowptr[i] = wsums[w] + inc - v;      // exclusive within block
    if (tid == SCAN_BS - 1) g_bsums[blockIdx.x] = wsums[31] + inc;
}

// ---------------------------------------------------------------------------
// 4. fused block-sum scan + apply: each block redundantly scans <=128 sums.
// ---------------------------------------------------------------------------
__global__ void scan3_kernel(int N, int nb) {
    __shared__ int wsum[4];
    __shared__ int pref;
    int tid = threadIdx.x;
    if (tid < 128) {
        int lane = tid & 31;
        int w = tid >> 5;
        int v = (tid < nb) ? g_bsums[tid] : 0;
        int inc = v;
        #pragma unroll
        for (int off = 1; off < 32; off <<= 1) {
            int t = __shfl_up_sync(0xffffffffu, inc, off);
            if (lane >= off) inc += t;
        }
        if (lane == 31) wsum[w] = inc;
    }
    __syncthreads();
    if (tid < 128) {
        int lane = tid & 31;
        int w = tid >> 5;
        int v = (tid < nb) ? g_bsums[tid] : 0;
        int inc = v;
        #pragma unroll
        for (int off = 1; off < 32; off <<= 1) {
            int t = __shfl_up_sync(0xffffffffu, inc, off);
            if (lane >= off) inc += t;
        }
        int base = 0;
        #pragma unroll
        for (int k = 0; k < 4; k++) base += (k < w) ? wsum[k] : 0;
        if (tid == blockIdx.x) pref = base + inc - v;   // exclusive prefix
    }
    __syncthreads();
    int i = blockIdx.x * SCAN_BS + tid;
    if (i < N) {
        int r = g_rowptr[i] + pref;
        g_rowptr[i] = r;
        g_cur[i] = r;
    }
}

// ---------------------------------------------------------------------------
// 5. scatter edges into CSR order with precomputed weights
// ---------------------------------------------------------------------------
__global__ void scatter_kernel(const int* __restrict__ n1,
                               const int* __restrict__ n2,
                               const float* __restrict__ dist,
                               int E) {
    int e = blockIdx.x * blockDim.x + threadIdx.x;
    if (e >= E) return;
    int a = n1[e];
    int c = n2[e];
    float dv = dist[e];
    float w = rsqrtf(__int2float_rn(g_degi[a]) * __int2float_rn(g_degi[c])) * __expf(-dv * dv);
    int pos = atomicAdd(&g_cur[a], 1);
    g_epack[pos] = make_int2(c, __float_as_int(w));
}

// ---------------------------------------------------------------------------
// 6. per-node gather-accumulate (fp32): 16 lanes per node, float4 per lane,
//    unroll-2 for MLP. Single write of agg row + weight sum. No atomics.
// ---------------------------------------------------------------------------
__global__ __launch_bounds__(256) void gather_kernel(const float* __restrict__ X,
                                                     float* __restrict__ out,
                                                     int N) {
    int gid = blockIdx.x * blockDim.x + threadIdx.x;
    int v = gid >> 4;            // node id
    int sub = gid & 15;          // float4 chunk within the 64-float row
    if (v >= N) return;

    int start = g_rowptr[v];
    int cnt = g_degi[v];
    const float4* X4 = reinterpret_cast<const float4*>(X);

    float4 acc = make_float4(0.f, 0.f, 0.f, 0.f);
    float swl = 0.0f;
    int j = 0;
    for (; j + 2 <= cnt; j += 2) {
        int2 p0 = g_epack[start + j];
        int2 p1 = g_epack[start + j + 1];
        float4 x0 = X4[(size_t)p0.x * 16 + sub];
        float4 x1 = X4[(size_t)p1.x * 16 + sub];
        float w0 = __int_as_float(p0.y);
        float w1 = __int_as_float(p1.y);
        swl += w0 + w1;
        acc.x = fmaf(w0, x0.x, acc.x);
        acc.y = fmaf(w0, x0.y, acc.y);
        acc.z = fmaf(w0, x0.z, acc.z);
        acc.w = fmaf(w0, x0.w, acc.w);
        acc.x = fmaf(w1, x1.x, acc.x);
        acc.y = fmaf(w1, x1.y, acc.y);
        acc.z = fmaf(w1, x1.z, acc.z);
        acc.w = fmaf(w1, x1.w, acc.w);
    }
    if (j < cnt) {
        int2 p = g_epack[start + j];
        float w = __int_as_float(p.y);
        float4 x = X4[(size_t)p.x * 16 + sub];
        swl += w;
        acc.x = fmaf(w, x.x, acc.x);
        acc.y = fmaf(w, x.y, acc.y);
        acc.z = fmaf(w, x.z, acc.z);
        acc.w = fmaf(w, x.w, acc.w);
    }
    reinterpret_cast<float4*>(out)[(size_t)v * 16 + sub] = acc;
    if (sub == 0) g_sw[v] = swl;
}

// ---------------------------------------------------------------------------
// 7. Post: y = agg @ W^T + sw*b, leaky_relu, L2 normalize. In-place on out.
// ---------------------------------------------------------------------------
#define PB_ROWS 64
#define WPITCH 33
#define XPITCH 66
__global__ __launch_bounds__(256) void post_kernel(const float* __restrict__ W,
                                                   const float* __restrict__ b,
                                                   float* __restrict__ out, int N) {
    __shared__ u64 Ws2[D * WPITCH];
    __shared__ u64 Xst2[(D / 2) * XPITCH];
    __shared__ float sws[PB_ROWS];

    int tid = threadIdx.x;
    int wid = tid >> 5;
    int l = tid & 31;
    int row0 = blockIdx.x * PB_ROWS;

    const u64* W2 = reinterpret_cast<const u64*>(W);
    #pragma unroll
    for (int i = tid; i < D * (D / 2); i += 256) {
        int j = i >> 5, kp = i & 31;
        Ws2[j * WPITCH + kp] = W2[i];
    }
    const u64* O2 = reinterpret_cast<const u64*>(out);
    #pragma unroll
    for (int i = tid; i < PB_ROWS * (D / 2); i += 256) {
        int r = i >> 5, kp = i & 31;
        int row = row0 + r;
        Xst2[kp * XPITCH + r] = (row < N) ? O2[(size_t)row * (D / 2) + kp] : 0ull;
    }
    if (tid < PB_ROWS) {
        int row = row0 + tid;
        sws[tid] = (row < N) ? g_sw[row] : 0.0f;
    }
    __syncthreads();

    int r0 = wid * 8;
    float bl = b[l], bh = b[l + 32];
    u64 accL[8], accH[8];
    #pragma unroll
    for (int r = 0; r < 8; r++) {
        float s = sws[r0 + r];
        accL[r] = pack2(s * bl, 0.0f);
        accH[r] = pack2(s * bh, 0.0f);
    }

    const u64* wrowL = &Ws2[l * WPITCH];
    const u64* wrowH = &Ws2[(l + 32) * WPITCH];
    #pragma unroll 2
    for (int kp = 0; kp < D / 2; kp++) {
        const u64* xr = &Xst2[kp * XPITCH + r0];
        ulonglong2 x01 = *reinterpret_cast<const ulonglong2*>(xr);
        ulonglong2 x23 = *reinterpret_cast<const ulonglong2*>(xr + 2);
        ulonglong2 x45 = *reinterpret_cast<const ulonglong2*>(xr + 4);
        ulonglong2 x67 = *reinterpret_cast<const ulonglong2*>(xr + 6);
        u64 wl = wrowL[kp];
        u64 wh = wrowH[kp];
        accL[0] = ffma2(x01.x, wl, accL[0]);  accH[0] = ffma2(x01.x, wh, accH[0]);
        accL[1] = ffma2(x01.y, wl, accL[1]);  accH[1] = ffma2(x01.y, wh, accH[1]);
        accL[2] = ffma2(x23.x, wl, accL[2]);  accH[2] = ffma2(x23.x, wh, accH[2]);
        accL[3] = ffma2(x23.y, wl, accL[3]);  accH[3] = ffma2(x23.y, wh, accH[3]);
        accL[4] = ffma2(x45.x, wl, accL[4]);  accH[4] = ffma2(x45.x, wh, accH[4]);
        accL[5] = ffma2(x45.y, wl, accL[5]);  accH[5] = ffma2(x45.y, wh, accH[5]);
        accL[6] = ffma2(x67.x, wl, accL[6]);  accH[6] = ffma2(x67.x, wh, accH[6]);
        accL[7] = ffma2(x67.y, wl, accL[7]);  accH[7] = ffma2(x67.y, wh, accH[7]);
    }

    #pragma unroll
    for (int r = 0; r < 8; r++) {
        float vL = lo32(accL[r]) + hi32(accL[r]);
        float vH = lo32(accH[r]) + hi32(accH[r]);
        vL = (vL >= 0.0f) ? vL : 0.01f * vL;
        vH = (vH >= 0.0f) ? vH : 0.01f * vH;
        float ss = vL * vL + vH * vH;
        #pragma unroll
        for (int o = 16; o > 0; o >>= 1) ss += __shfl_xor_sync(0xffffffffu, ss, o);
        int row = row0 + r0 + r;
        if (row < N) {
            float inv = 1.0f / fmaxf(sqrtf(ss), 1e-12f);
            out[(size_t)row * D + l]      = vL * inv;
            out[(size_t)row * D + l + 32] = vH * inv;
        }
    }
}

// ---------------------------------------------------------------------------
// Launch
// ---------------------------------------------------------------------------
extern "C" void kernel_launch(void* const* d_in, const int* in_sizes, int n_in,
                              void* d_out, int out_size) {
    const float* poi  = (const float*)d_in[0];
    const int*   eidx = (const int*)d_in[1];
    const float* dist = (const float*)d_in[2];
    const float* W    = (const float*)d_in[3];
    const float* b    = (const float*)d_in[4];
    float* out = (float*)d_out;

    int N = in_sizes[0] / D;
    int E = in_sizes[1] / 2;
    const int* n1 = eidx;
    const int* n2 = eidx + E;
    int nb = (N + SCAN_BS - 1) / SCAN_BS;

    zero_deg_kernel<<<(N + 255) / 256, 256>>>(N);
    deg_kernel<<<(E + 255) / 256, 256>>>(n1, E);
    scan1_kernel<<<nb, SCAN_BS>>>(N);
    scan3_kernel<<<nb, SCAN_BS>>>(N, nb);
    scatter_kernel<<<(E + 255) / 256, 256>>>(n1, n2, dist, E);
    {
        long long threads = (long long)N * 16;
        int blocks = (int)((threads + 255) / 256);
        gather_kernel<<<blocks, 256>>>(poi, out, N);
    }
    {
        int blocks = (N + PB_ROWS - 1) / PB_ROWS;
        post_kernel<<<blocks, 256>>>(W, b, out, N);
    }
}